// round 2
// baseline (speedup 1.0000x reference)
#include <cuda_runtime.h>
#include <cstdint>

// Scratch: packed (sortable_value:32 | (N-j):32) per (k, c), channel-interleaved
// layout acc[k*C + c] so one point's 64 channel-atomics are contiguous (512B).
// 32M u64 = 256MB static device scratch (C*N = 64*500000 = 32,000,000).
__device__ unsigned long long g_acc[32000000];

__device__ __forceinline__ unsigned f2sort(float f) {
    unsigned u = __float_as_uint(f);
    return (u & 0x80000000u) ? ~u : (u | 0x80000000u);
}
__device__ __forceinline__ float sort2f(unsigned s) {
    unsigned u = (s & 0x80000000u) ? (s ^ 0x80000000u) : ~s;
    return __uint_as_float(u);
}

// -------------------- Pass 1: scatter (one thread per point j) --------------------
// src reads: lane = j -> coalesced 128B per channel row.
// atomics: 64 consecutive u64 per thread (same k) -> contiguous lines, REDG.
__global__ void scatter64_kernel(const float* __restrict__ src,
                                 const int* __restrict__ index,
                                 int N) {
    int j = blockIdx.x * blockDim.x + threadIdx.x;
    if (j >= N) return;
    int k = index[j];
    unsigned long long* accp = g_acc + (size_t)k * 64;
    unsigned lowkey = (unsigned)(N - j);   // larger lowkey <=> smaller j (tie-break)
    const float* sp = src + j;
#pragma unroll 8
    for (int c = 0; c < 64; ++c) {
        float v = __ldg(sp + (size_t)c * N);
        unsigned long long p = ((unsigned long long)f2sort(v) << 32) | (unsigned long long)lowkey;
        atomicMax(accp + c, p);
    }
}

// -------------------- Pass 2: finalize with smem transpose --------------------
// Block handles 64 consecutive k. Phase A: coalesced u64 reads of acc (k*64+c),
// decode into smem[kk][c]. Phase B: row-major coalesced writes of out/arg.
__global__ void finalize64_kernel(const float* __restrict__ src,
                                  float* __restrict__ out,
                                  float* __restrict__ arg,
                                  int N, int writeArg) {
    __shared__ float s_val[64][65];
    __shared__ int   s_arg[64][65];
    int k0 = blockIdx.x * 64;
    int tid = threadIdx.x;

    // Phase A: read acc[(k0+kk)*64 + c], e = kk*64 + c
    for (int e = tid; e < 64 * 64; e += blockDim.x) {
        int kk = e >> 6;
        int c  = e & 63;
        int k  = k0 + kk;
        float val = __int_as_float(0xff800000); // -inf
        int   a   = N;
        if (k < N) {
            unsigned long long p = g_acc[(size_t)k0 * 64 + e];
            unsigned low = (unsigned)p;
            unsigned hi  = (unsigned)(p >> 32);
            if (low != 0u) {               // non-empty segment
                val = sort2f(hi);
                a   = N - (int)low;        // smallest j achieving the max
            }
        }
        s_val[kk][c] = val;
        s_arg[kk][c] = a;
    }
    __syncthreads();

    // Phase B: e = c*64 + kk -> consecutive lanes walk kk => coalesced row writes
    for (int e = tid; e < 64 * 64; e += blockDim.x) {
        int c  = e >> 6;
        int kk = e & 63;
        int k  = k0 + kk;
        if (k < N) {
            size_t idx = (size_t)c * N + k;
            float sv  = src[idx];
            float seg = s_val[kk][c];
            float o   = fmaxf(sv, seg);
            int   a   = (seg >= sv) ? s_arg[kk][c] : N;
            out[idx] = o;
            if (writeArg) arg[idx] = (float)a;
        }
    }
}

// -------------------- Generic fallback (C != 64) --------------------
__global__ void scatter_gen_kernel(const float* __restrict__ src,
                                   const int* __restrict__ index,
                                   int C, int N) {
    int j = blockIdx.x * blockDim.x + threadIdx.x;
    if (j >= N) return;
    int k = index[j];
    unsigned long long* accp = g_acc + (size_t)k * C;
    unsigned lowkey = (unsigned)(N - j);
    for (int c = 0; c < C; ++c) {
        float v = __ldg(src + (size_t)c * N + j);
        unsigned long long p = ((unsigned long long)f2sort(v) << 32) | (unsigned long long)lowkey;
        atomicMax(accp + c, p);
    }
}

__global__ void finalize_gen_kernel(const float* __restrict__ src,
                                    float* __restrict__ out,
                                    float* __restrict__ arg,
                                    int C, int N, int writeArg) {
    long long t = (long long)blockIdx.x * blockDim.x + threadIdx.x;
    long long total = (long long)C * N;
    if (t >= total) return;
    int c = (int)(t / N);
    int k = (int)(t % N);
    unsigned long long p = g_acc[(size_t)k * C + c];
    unsigned low = (unsigned)p;
    unsigned hi  = (unsigned)(p >> 32);
    float seg = (low != 0u) ? sort2f(hi) : __int_as_float(0xff800000);
    int   a   = (low != 0u) ? (N - (int)low) : N;
    float sv = src[t];
    out[t] = fmaxf(sv, seg);
    if (writeArg) arg[t] = (float)((seg >= sv) ? a : N);
}

extern "C" void kernel_launch(void* const* d_in, const int* in_sizes, int n_in,
                              void* d_out, int out_size) {
    const float* src   = (const float*)d_in[0];
    const int*   index = (const int*)d_in[1];   // JAX x64-disabled: int64 request -> int32

    int N = in_sizes[1];
    int C = (N > 0) ? (in_sizes[0] / N) : 0;
    if (N <= 0 || C <= 0) return;

    size_t cn = (size_t)C * (size_t)N;

    void* accp = nullptr;
    cudaGetSymbolAddress(&accp, g_acc);
    cudaMemsetAsync(accp, 0, cn * sizeof(unsigned long long), 0);

    float* out = (float*)d_out;
    int writeArg = ((size_t)out_size >= 2 * cn) ? 1 : 0;
    float* arg = out + cn;  // second half: argmax as float (exact, N < 2^24)

    int threads = 256;
    if (C == 64) {
        scatter64_kernel<<<(N + threads - 1) / threads, threads>>>(src, index, N);
        finalize64_kernel<<<(N + 63) / 64, threads>>>(src, out, arg, N, writeArg);
    } else {
        scatter_gen_kernel<<<(N + threads - 1) / threads, threads>>>(src, index, C, N);
        long long total = (long long)C * N;
        finalize_gen_kernel<<<(int)((total + threads - 1) / threads), threads>>>(
            src, out, arg, C, N, writeArg);
    }
}

// round 3
// speedup vs baseline: 1.2896x; 1.2896x over previous
#include <cuda_runtime.h>
#include <cstdint>

// Scratch: packed (sortable_value:32 | (N-j):32) per (k, c), channel-interleaved
// acc[k*64 + c]. 32M u64 = 256MB static device scratch (C*N = 64*500000).
__device__ unsigned long long g_acc[32000000];

__device__ __forceinline__ unsigned f2sort(float f) {
    unsigned u = __float_as_uint(f);
    return (u & 0x80000000u) ? ~u : (u | 0x80000000u);
}
__device__ __forceinline__ float sort2f(unsigned s) {
    unsigned u = (s & 0x80000000u) ? (s ^ 0x80000000u) : ~s;
    return __uint_as_float(u);
}

// -------------------- Pass 1: scatter --------------------
// Block = 256 threads handles 64 points; each thread does 16 channels of one
// point (4 threads per point). Loads are front-batched into registers, then a
// burst of 16 REDG.64 atomics to contiguous addresses (4 32B sectors).
__global__ void scatter64_kernel(const float* __restrict__ src,
                                 const int* __restrict__ index,
                                 int N) {
    int w    = threadIdx.x >> 5;
    int lane = threadIdx.x & 31;
    int j  = blockIdx.x * 64 + ((w >> 2) << 5) + lane;  // consecutive j per lane
    int c0 = (w & 3) << 4;                              // 0,16,32,48
    if (j >= N) return;
    int k = index[j];
    unsigned lowkey = (unsigned)(N - j);   // larger lowkey <=> smaller j
    const float* sp = src + (size_t)c0 * N + j;
    unsigned long long* accp = g_acc + (size_t)k * 64 + c0;

    float v[16];
#pragma unroll
    for (int i = 0; i < 16; ++i) v[i] = __ldg(sp + (size_t)i * N);
#pragma unroll
    for (int i = 0; i < 16; ++i) {
        unsigned long long p =
            ((unsigned long long)f2sort(v[i]) << 32) | (unsigned long long)lowkey;
        atomicMax(accp + i, p);
    }
}

// -------------------- Pass 2: finalize (vectorized) --------------------
// Block handles a 64k x 64c tile. Phase A: longlong2 coalesced reads of acc,
// decode into smem[c][kk]. Phase B: float4 src reads + float4 out/arg writes.
__global__ void finalize64_kernel(const float* __restrict__ src,
                                  float* __restrict__ out,
                                  float* __restrict__ arg,
                                  int N, int writeArg) {
    __shared__ float s_val[64][65];
    __shared__ float s_arg[64][65];
    int k0  = blockIdx.x * 64;
    int tid = threadIdx.x;

    if (k0 + 64 <= N) {
        // ---- fast path (full tile) ----
        const longlong2* accv =
            reinterpret_cast<const longlong2*>(g_acc + (size_t)k0 * 64);
#pragma unroll
        for (int i = 0; i < 8; ++i) {
            int idx = i * 512 + tid * 2;            // element index in tile
            longlong2 p2 = accv[idx >> 1];
            int kk = idx >> 6;
            int c  = idx & 63;
            {
                unsigned long long p = (unsigned long long)p2.x;
                unsigned low = (unsigned)p, hi = (unsigned)(p >> 32);
                s_val[c][kk] = low ? sort2f(hi) : __int_as_float(0xff800000);
                s_arg[c][kk] = (float)(low ? (N - (int)low) : N);
            }
            {
                unsigned long long p = (unsigned long long)p2.y;
                unsigned low = (unsigned)p, hi = (unsigned)(p >> 32);
                s_val[c + 1][kk] = low ? sort2f(hi) : __int_as_float(0xff800000);
                s_arg[c + 1][kk] = (float)(low ? (N - (int)low) : N);
            }
        }
        __syncthreads();

        float fN = (float)N;
#pragma unroll
        for (int i = 0; i < 4; ++i) {
            int e   = i * 1024 + tid * 4;
            int c   = e >> 6;
            int kk  = e & 63;
            size_t gidx = (size_t)c * N + (k0 + kk);
            float4 sv = *reinterpret_cast<const float4*>(src + gidx);
            float4 ov, av;
            {
                float seg = s_val[c][kk + 0];
                ov.x = fmaxf(sv.x, seg);
                av.x = (seg >= sv.x) ? s_arg[c][kk + 0] : fN;
            }
            {
                float seg = s_val[c][kk + 1];
                ov.y = fmaxf(sv.y, seg);
                av.y = (seg >= sv.y) ? s_arg[c][kk + 1] : fN;
            }
            {
                float seg = s_val[c][kk + 2];
                ov.z = fmaxf(sv.z, seg);
                av.z = (seg >= sv.z) ? s_arg[c][kk + 2] : fN;
            }
            {
                float seg = s_val[c][kk + 3];
                ov.w = fmaxf(sv.w, seg);
                av.w = (seg >= sv.w) ? s_arg[c][kk + 3] : fN;
            }
            *reinterpret_cast<float4*>(out + gidx) = ov;
            if (writeArg) *reinterpret_cast<float4*>(arg + gidx) = av;
        }
    } else {
        // ---- partial tile (last block): scalar guarded path ----
        for (int e = tid; e < 64 * 64; e += blockDim.x) {
            int kk = e >> 6;
            int c  = e & 63;
            int k  = k0 + kk;
            float val = __int_as_float(0xff800000);
            int a = N;
            if (k < N) {
                unsigned long long p = g_acc[(size_t)k0 * 64 + e];
                unsigned low = (unsigned)p, hi = (unsigned)(p >> 32);
                if (low) { val = sort2f(hi); a = N - (int)low; }
            }
            s_val[c][kk] = val;  // note transposed vs index order: c = e&63
            s_arg[c][kk] = (float)a;
        }
        __syncthreads();
        for (int e = tid; e < 64 * 64; e += blockDim.x) {
            int c  = e >> 6;
            int kk = e & 63;
            int k  = k0 + kk;
            if (k < N) {
                size_t idx = (size_t)c * N + k;
                float sv  = src[idx];
                // smem was filled with [c][kk] where that c was e&63 of the
                // element index kk*64+c -> same (c,kk) mapping; read matches.
                float seg = s_val[c][kk];
                out[idx] = fmaxf(sv, seg);
                if (writeArg) arg[idx] = (seg >= sv) ? s_arg[c][kk] : (float)N;
            }
        }
    }
}

// -------------------- Generic fallback (C != 64) --------------------
__global__ void scatter_gen_kernel(const float* __restrict__ src,
                                   const int* __restrict__ index,
                                   int C, int N) {
    int j = blockIdx.x * blockDim.x + threadIdx.x;
    if (j >= N) return;
    int k = index[j];
    unsigned long long* accp = g_acc + (size_t)k * C;
    unsigned lowkey = (unsigned)(N - j);
    for (int c = 0; c < C; ++c) {
        float v = __ldg(src + (size_t)c * N + j);
        unsigned long long p =
            ((unsigned long long)f2sort(v) << 32) | (unsigned long long)lowkey;
        atomicMax(accp + c, p);
    }
}

__global__ void finalize_gen_kernel(const float* __restrict__ src,
                                    float* __restrict__ out,
                                    float* __restrict__ arg,
                                    int C, int N, int writeArg) {
    long long t = (long long)blockIdx.x * blockDim.x + threadIdx.x;
    long long total = (long long)C * N;
    if (t >= total) return;
    int c = (int)(t / N);
    int k = (int)(t % N);
    unsigned long long p = g_acc[(size_t)k * C + c];
    unsigned low = (unsigned)p, hi = (unsigned)(p >> 32);
    float seg = low ? sort2f(hi) : __int_as_float(0xff800000);
    int   a   = low ? (N - (int)low) : N;
    float sv = src[t];
    out[t] = fmaxf(sv, seg);
    if (writeArg) arg[t] = (float)((seg >= sv) ? a : N);
}

extern "C" void kernel_launch(void* const* d_in, const int* in_sizes, int n_in,
                              void* d_out, int out_size) {
    const float* src   = (const float*)d_in[0];
    const int*   index = (const int*)d_in[1];   // JAX x64-disabled: int32

    int N = in_sizes[1];
    int C = (N > 0) ? (in_sizes[0] / N) : 0;
    if (N <= 0 || C <= 0) return;

    size_t cn = (size_t)C * (size_t)N;

    void* accp = nullptr;
    cudaGetSymbolAddress(&accp, g_acc);
    cudaMemsetAsync(accp, 0, cn * sizeof(unsigned long long), 0);

    float* out = (float*)d_out;
    int writeArg = ((size_t)out_size >= 2 * cn) ? 1 : 0;
    float* arg = out + cn;

    if (C == 64) {
        scatter64_kernel<<<(N + 63) / 64, 256>>>(src, index, N);
        finalize64_kernel<<<(N + 63) / 64, 256>>>(src, out, arg, N, writeArg);
    } else {
        int threads = 256;
        scatter_gen_kernel<<<(N + threads - 1) / threads, threads>>>(src, index, C, N);
        long long total = (long long)C * N;
        finalize_gen_kernel<<<(int)((total + threads - 1) / threads), threads>>>(
            src, out, arg, C, N, writeArg);
    }
}

// round 4
// speedup vs baseline: 1.3427x; 1.0411x over previous
#include <cuda_runtime.h>
#include <cstdint>

// Scratch: packed (sortable_value:32 | (N-j):32) per (k, c), acc[k*64 + c].
// 32M u64 = 256MB static device scratch (C*N = 64*500000).
__device__ unsigned long long g_acc[32000000];

__device__ __forceinline__ unsigned f2sort(float f) {
    unsigned u = __float_as_uint(f);
    return (u & 0x80000000u) ? ~u : (u | 0x80000000u);
}
__device__ __forceinline__ float sort2f(unsigned s) {
    unsigned u = (s & 0x80000000u) ? (s ^ 0x80000000u) : ~s;
    return __uint_as_float(u);
}

// -------------------- Pass 1: scatter (k-range partitioned) --------------------
// 4 threads per point, 16 channels each. Only points with klo <= index[j] < khi
// are processed, so the active half of the scratch (zeroed immediately before
// by memset, which warms L2) stays ~L2-resident during the atomic RMWs.
// src/index loads use __ldcs (evict-first) to avoid evicting scratch lines.
__global__ void scatter64_kernel(const float* __restrict__ src,
                                 const int* __restrict__ index,
                                 int N, int klo, int khi) {
    int w    = threadIdx.x >> 5;
    int lane = threadIdx.x & 31;
    int j  = blockIdx.x * 64 + ((w >> 2) << 5) + lane;  // consecutive j per lane
    int c0 = (w & 3) << 4;                              // 0,16,32,48
    if (j >= N) return;
    int k = __ldcs(index + j);
    if (k < klo || k >= khi) return;
    unsigned lowkey = (unsigned)(N - j);   // larger lowkey <=> smaller j
    const float* sp = src + (size_t)c0 * N + j;
    unsigned long long* accp = g_acc + (size_t)k * 64 + c0;

    float v[16];
#pragma unroll
    for (int i = 0; i < 16; ++i) v[i] = __ldcs(sp + (size_t)i * N);
#pragma unroll
    for (int i = 0; i < 16; ++i) {
        unsigned long long p =
            ((unsigned long long)f2sort(v[i]) << 32) | (unsigned long long)lowkey;
        atomicMax(accp + i, p);
    }
}

// -------------------- Pass 2: finalize (vectorized) --------------------
__global__ void finalize64_kernel(const float* __restrict__ src,
                                  float* __restrict__ out,
                                  float* __restrict__ arg,
                                  int N, int writeArg) {
    __shared__ __align__(16) float s_val[64][68];
    __shared__ __align__(16) float s_arg[64][68];
    int k0  = blockIdx.x * 64;
    int tid = threadIdx.x;

    if (k0 + 64 <= N) {
        // ---- fast path (full tile) ----
        const longlong2* accv =
            reinterpret_cast<const longlong2*>(g_acc + (size_t)k0 * 64);
#pragma unroll
        for (int i = 0; i < 8; ++i) {
            int idx = i * 512 + tid * 2;            // element index in tile
            longlong2 p2 = __ldcs(accv + (idx >> 1));
            int kk = idx >> 6;
            int c  = idx & 63;
            {
                unsigned long long p = (unsigned long long)p2.x;
                unsigned low = (unsigned)p, hi = (unsigned)(p >> 32);
                s_val[c][kk] = low ? sort2f(hi) : __int_as_float(0xff800000);
                s_arg[c][kk] = (float)(low ? (N - (int)low) : N);
            }
            {
                unsigned long long p = (unsigned long long)p2.y;
                unsigned low = (unsigned)p, hi = (unsigned)(p >> 32);
                s_val[c + 1][kk] = low ? sort2f(hi) : __int_as_float(0xff800000);
                s_arg[c + 1][kk] = (float)(low ? (N - (int)low) : N);
            }
        }
        __syncthreads();

        float fN = (float)N;
#pragma unroll
        for (int i = 0; i < 4; ++i) {
            int e   = i * 1024 + tid * 4;
            int c   = e >> 6;
            int kk  = e & 63;
            size_t gidx = (size_t)c * N + (k0 + kk);
            float4 sv = __ldcs(reinterpret_cast<const float4*>(src + gidx));
            float4 sg = *reinterpret_cast<const float4*>(&s_val[c][kk]);
            float4 sa = *reinterpret_cast<const float4*>(&s_arg[c][kk]);
            float4 ov, av;
            ov.x = fmaxf(sv.x, sg.x); av.x = (sg.x >= sv.x) ? sa.x : fN;
            ov.y = fmaxf(sv.y, sg.y); av.y = (sg.y >= sv.y) ? sa.y : fN;
            ov.z = fmaxf(sv.z, sg.z); av.z = (sg.z >= sv.z) ? sa.z : fN;
            ov.w = fmaxf(sv.w, sg.w); av.w = (sg.w >= sv.w) ? sa.w : fN;
            __stcs(reinterpret_cast<float4*>(out + gidx), ov);
            if (writeArg) __stcs(reinterpret_cast<float4*>(arg + gidx), av);
        }
    } else {
        // ---- partial tile (last block): scalar guarded path ----
        for (int e = tid; e < 64 * 64; e += blockDim.x) {
            int kk = e >> 6;
            int c  = e & 63;
            int k  = k0 + kk;
            float val = __int_as_float(0xff800000);
            int a = N;
            if (k < N) {
                unsigned long long p = g_acc[(size_t)k0 * 64 + e];
                unsigned low = (unsigned)p, hi = (unsigned)(p >> 32);
                if (low) { val = sort2f(hi); a = N - (int)low; }
            }
            s_val[c][kk] = val;
            s_arg[c][kk] = (float)a;
        }
        __syncthreads();
        for (int e = tid; e < 64 * 64; e += blockDim.x) {
            int c  = e >> 6;
            int kk = e & 63;
            int k  = k0 + kk;
            if (k < N) {
                size_t idx = (size_t)c * N + k;
                float sv  = src[idx];
                float seg = s_val[c][kk];
                out[idx] = fmaxf(sv, seg);
                if (writeArg) arg[idx] = (seg >= sv) ? s_arg[c][kk] : (float)N;
            }
        }
    }
}

// -------------------- Generic fallback (C != 64) --------------------
__global__ void scatter_gen_kernel(const float* __restrict__ src,
                                   const int* __restrict__ index,
                                   int C, int N) {
    int j = blockIdx.x * blockDim.x + threadIdx.x;
    if (j >= N) return;
    int k = index[j];
    unsigned long long* accp = g_acc + (size_t)k * C;
    unsigned lowkey = (unsigned)(N - j);
    for (int c = 0; c < C; ++c) {
        float v = __ldg(src + (size_t)c * N + j);
        unsigned long long p =
            ((unsigned long long)f2sort(v) << 32) | (unsigned long long)lowkey;
        atomicMax(accp + c, p);
    }
}

__global__ void finalize_gen_kernel(const float* __restrict__ src,
                                    float* __restrict__ out,
                                    float* __restrict__ arg,
                                    int C, int N, int writeArg) {
    long long t = (long long)blockIdx.x * blockDim.x + threadIdx.x;
    long long total = (long long)C * N;
    if (t >= total) return;
    int c = (int)(t / N);
    int k = (int)(t % N);
    unsigned long long p = g_acc[(size_t)k * C + c];
    unsigned low = (unsigned)p, hi = (unsigned)(p >> 32);
    float seg = low ? sort2f(hi) : __int_as_float(0xff800000);
    int   a   = low ? (N - (int)low) : N;
    float sv = src[t];
    out[t] = fmaxf(sv, seg);
    if (writeArg) arg[t] = (float)((seg >= sv) ? a : N);
}

extern "C" void kernel_launch(void* const* d_in, const int* in_sizes, int n_in,
                              void* d_out, int out_size) {
    const float* src   = (const float*)d_in[0];
    const int*   index = (const int*)d_in[1];   // JAX x64-disabled: int32

    int N = in_sizes[1];
    int C = (N > 0) ? (in_sizes[0] / N) : 0;
    if (N <= 0 || C <= 0) return;

    size_t cn = (size_t)C * (size_t)N;

    unsigned char* accp = nullptr;
    cudaGetSymbolAddress((void**)&accp, g_acc);

    float* out = (float*)d_out;
    int writeArg = ((size_t)out_size >= 2 * cn) ? 1 : 0;
    float* arg = out + cn;

    if (C == 64) {
        int kmid = N / 2;
        size_t half0 = (size_t)kmid * 64 * sizeof(unsigned long long);
        size_t rest  = cn * sizeof(unsigned long long) - half0;
        int blocks = (N + 63) / 64;
        // memset half -> scatter into that half (memset warms L2 with the lines)
        cudaMemsetAsync(accp, 0, half0, 0);
        scatter64_kernel<<<blocks, 256>>>(src, index, N, 0, kmid);
        cudaMemsetAsync(accp + half0, 0, rest, 0);
        scatter64_kernel<<<blocks, 256>>>(src, index, N, kmid, N);
        finalize64_kernel<<<blocks, 256>>>(src, out, arg, N, writeArg);
    } else {
        cudaMemsetAsync(accp, 0, cn * sizeof(unsigned long long), 0);
        int threads = 256;
        scatter_gen_kernel<<<(N + threads - 1) / threads, threads>>>(src, index, C, N);
        long long total = (long long)C * N;
        finalize_gen_kernel<<<(int)((total + threads - 1) / threads), threads>>>(
            src, out, arg, C, N, writeArg);
    }
}

// round 5
// speedup vs baseline: 1.5559x; 1.1588x over previous
#include <cuda_runtime.h>
#include <cstdint>

// Scratch: 4 channel-groups, each acc_g[k*16 + cc] packed
// (sortable_value:32 | (N-j):32). Group footprint = N*16*8B = 64MB (L2-resident).
// 32M u64 = 256MB total (C*N = 64*500000).
__device__ unsigned long long g_acc[32000000];

__device__ __forceinline__ unsigned f2sort(float f) {
    unsigned u = __float_as_uint(f);
    return (u & 0x80000000u) ? ~u : (u | 0x80000000u);
}
__device__ __forceinline__ float sort2f(unsigned s) {
    unsigned u = (s & 0x80000000u) ? (s ^ 0x80000000u) : ~s;
    return __uint_as_float(u);
}

// -------------------- Pass 1: scatter, one channel-group (16 ch) --------------------
// 1 thread per point: 16 coalesced src loads (dense rows c0..c0+15), then 16
// contiguous REDG.64 into the group's 64MB L2-resident scratch.
__global__ void scatter16_kernel(const float* __restrict__ src,
                                 const int* __restrict__ index,
                                 int N, int c0,
                                 unsigned long long* __restrict__ acc) {
    int j = blockIdx.x * blockDim.x + threadIdx.x;
    if (j >= N) return;
    int k = __ldcs(index + j);
    unsigned lowkey = (unsigned)(N - j);   // larger lowkey <=> smaller j
    const float* sp = src + (size_t)c0 * N + j;
    unsigned long long* ap = acc + (size_t)k * 16;

    float v[16];
#pragma unroll
    for (int i = 0; i < 16; ++i) v[i] = __ldcs(sp + (size_t)i * N);
#pragma unroll
    for (int i = 0; i < 16; ++i) {
        unsigned long long p =
            ((unsigned long long)f2sort(v[i]) << 32) | (unsigned long long)lowkey;
        atomicMax(ap + i, p);
    }
}

// -------------------- Pass 2: finalize (vectorized, 512 threads) --------------------
__global__ void finalize64_kernel(const float* __restrict__ src,
                                  float* __restrict__ out,
                                  float* __restrict__ arg,
                                  int N, int writeArg) {
    __shared__ __align__(16) float s_val[64][68];
    __shared__ __align__(16) float s_arg[64][68];
    int k0  = blockIdx.x * 64;
    int tid = threadIdx.x;
    size_t grpStride = (size_t)N * 16;

    if (k0 + 64 <= N) {
        // ---- fast path: phase A, one longlong2 per thread per group ----
#pragma unroll
        for (int g = 0; g < 4; ++g) {
            const longlong2* accv = reinterpret_cast<const longlong2*>(
                g_acc + (size_t)g * grpStride + (size_t)k0 * 16);
            int idx = tid * 2;                 // 0..1022, within 1024 u64 tile
            longlong2 p2 = __ldcs(accv + tid);
            int kk = idx >> 4;
            int c  = g * 16 + (idx & 15);
            {
                unsigned long long p = (unsigned long long)p2.x;
                unsigned low = (unsigned)p, hi = (unsigned)(p >> 32);
                s_val[c][kk] = low ? sort2f(hi) : __int_as_float(0xff800000);
                s_arg[c][kk] = (float)(low ? (N - (int)low) : N);
            }
            {
                unsigned long long p = (unsigned long long)p2.y;
                unsigned low = (unsigned)p, hi = (unsigned)(p >> 32);
                s_val[c + 1][kk] = low ? sort2f(hi) : __int_as_float(0xff800000);
                s_arg[c + 1][kk] = (float)(low ? (N - (int)low) : N);
            }
        }
        __syncthreads();

        float fN = (float)N;
#pragma unroll
        for (int i = 0; i < 2; ++i) {
            int e   = i * 2048 + tid * 4;      // 64c x 64kk floats
            int c   = e >> 6;
            int kk  = e & 63;
            size_t gidx = (size_t)c * N + (k0 + kk);
            float4 sv = __ldcs(reinterpret_cast<const float4*>(src + gidx));
            float4 sg = *reinterpret_cast<const float4*>(&s_val[c][kk]);
            float4 sa = *reinterpret_cast<const float4*>(&s_arg[c][kk]);
            float4 ov, av;
            ov.x = fmaxf(sv.x, sg.x); av.x = (sg.x >= sv.x) ? sa.x : fN;
            ov.y = fmaxf(sv.y, sg.y); av.y = (sg.y >= sv.y) ? sa.y : fN;
            ov.z = fmaxf(sv.z, sg.z); av.z = (sg.z >= sv.z) ? sa.z : fN;
            ov.w = fmaxf(sv.w, sg.w); av.w = (sg.w >= sv.w) ? sa.w : fN;
            __stcs(reinterpret_cast<float4*>(out + gidx), ov);
            if (writeArg) __stcs(reinterpret_cast<float4*>(arg + gidx), av);
        }
    } else {
        // ---- partial tile (last block): scalar guarded path ----
        for (int e = tid; e < 64 * 64; e += blockDim.x) {
            int kk = e >> 6;
            int c  = e & 63;
            int k  = k0 + kk;
            float val = __int_as_float(0xff800000);
            int a = N;
            if (k < N) {
                int g  = c >> 4;
                int cc = c & 15;
                unsigned long long p =
                    g_acc[(size_t)g * grpStride + (size_t)k * 16 + cc];
                unsigned low = (unsigned)p, hi = (unsigned)(p >> 32);
                if (low) { val = sort2f(hi); a = N - (int)low; }
            }
            s_val[c][kk] = val;
            s_arg[c][kk] = (float)a;
        }
        __syncthreads();
        for (int e = tid; e < 64 * 64; e += blockDim.x) {
            int c  = e >> 6;
            int kk = e & 63;
            int k  = k0 + kk;
            if (k < N) {
                size_t idx = (size_t)c * N + k;
                float sv  = src[idx];
                float seg = s_val[c][kk];
                out[idx] = fmaxf(sv, seg);
                if (writeArg) arg[idx] = (seg >= sv) ? s_arg[c][kk] : (float)N;
            }
        }
    }
}

// -------------------- Generic fallback (C != 64) --------------------
__global__ void scatter_gen_kernel(const float* __restrict__ src,
                                   const int* __restrict__ index,
                                   int C, int N) {
    int j = blockIdx.x * blockDim.x + threadIdx.x;
    if (j >= N) return;
    int k = index[j];
    unsigned long long* accp = g_acc + (size_t)k * C;
    unsigned lowkey = (unsigned)(N - j);
    for (int c = 0; c < C; ++c) {
        float v = __ldg(src + (size_t)c * N + j);
        unsigned long long p =
            ((unsigned long long)f2sort(v) << 32) | (unsigned long long)lowkey;
        atomicMax(accp + c, p);
    }
}

__global__ void finalize_gen_kernel(const float* __restrict__ src,
                                    float* __restrict__ out,
                                    float* __restrict__ arg,
                                    int C, int N, int writeArg) {
    long long t = (long long)blockIdx.x * blockDim.x + threadIdx.x;
    long long total = (long long)C * N;
    if (t >= total) return;
    int c = (int)(t / N);
    int k = (int)(t % N);
    unsigned long long p = g_acc[(size_t)k * C + c];
    unsigned low = (unsigned)p, hi = (unsigned)(p >> 32);
    float seg = low ? sort2f(hi) : __int_as_float(0xff800000);
    int   a   = low ? (N - (int)low) : N;
    float sv = src[t];
    out[t] = fmaxf(sv, seg);
    if (writeArg) arg[t] = (float)((seg >= sv) ? a : N);
}

extern "C" void kernel_launch(void* const* d_in, const int* in_sizes, int n_in,
                              void* d_out, int out_size) {
    const float* src   = (const float*)d_in[0];
    const int*   index = (const int*)d_in[1];   // JAX x64-disabled: int32

    int N = in_sizes[1];
    int C = (N > 0) ? (in_sizes[0] / N) : 0;
    if (N <= 0 || C <= 0) return;

    size_t cn = (size_t)C * (size_t)N;

    unsigned char* accp = nullptr;
    cudaGetSymbolAddress((void**)&accp, g_acc);

    float* out = (float*)d_out;
    int writeArg = ((size_t)out_size >= 2 * cn) ? 1 : 0;
    float* arg = out + cn;

    if (C == 64) {
        size_t grpBytes = (size_t)N * 16 * sizeof(unsigned long long); // 64MB
        int sBlocks = (N + 255) / 256;
        for (int g = 0; g < 4; ++g) {
            // memset warms L2 with zeroed lines; scatter's atomics then hit L2
            cudaMemsetAsync(accp + (size_t)g * grpBytes, 0, grpBytes, 0);
            scatter16_kernel<<<sBlocks, 256>>>(
                src, index, N, g * 16,
                reinterpret_cast<unsigned long long*>(accp + (size_t)g * grpBytes));
        }
        finalize64_kernel<<<(N + 63) / 64, 512>>>(src, out, arg, N, writeArg);
    } else {
        cudaMemsetAsync(accp, 0, cn * sizeof(unsigned long long), 0);
        int threads = 256;
        scatter_gen_kernel<<<(N + threads - 1) / threads, threads>>>(src, index, C, N);
        long long total = (long long)C * N;
        finalize_gen_kernel<<<(int)((total + threads - 1) / threads), threads>>>(
            src, out, arg, C, N, writeArg);
    }
}

// round 6
// speedup vs baseline: 1.6441x; 1.0567x over previous
#include <cuda_runtime.h>
#include <cstdint>

// Scratch: 4 channel-groups, each acc_g[k*16 + cc] packed
// (sortable_value:32 | (N-j):32). Group footprint = N*16*8B = 64MB (L2-resident).
__device__ unsigned long long g_acc[32000000];

__device__ __forceinline__ unsigned f2sort(float f) {
    unsigned u = __float_as_uint(f);
    return (u & 0x80000000u) ? ~u : (u | 0x80000000u);
}
__device__ __forceinline__ float sort2f(unsigned s) {
    unsigned u = (s & 0x80000000u) ? (s ^ 0x80000000u) : ~s;
    return __uint_as_float(u);
}

// -------------------- Pass 1: scatter, one channel-group (16 ch) --------------------
// Each thread: 4 consecutive points x 8 channels. src loads are LDG.128
// (float4 over j), so LSU ops/element drop from 2.0 to 1.25 (atomics are the
// irreducible part). half = tid&1 picks channels [c0+0..7] or [c0+8..15].
__global__ void scatter16_kernel(const float* __restrict__ src,
                                 const int* __restrict__ index,
                                 int N, int c0,
                                 unsigned long long* __restrict__ acc) {
    int t    = threadIdx.x;
    int half = t & 1;
    int g    = t >> 1;
    int j0   = blockIdx.x * 512 + g * 4;
    if (j0 >= N) return;
    int ch0 = c0 + half * 8;   // absolute first channel for this thread
    int cc0 = half * 8;        // channel offset within group

    if (j0 + 4 <= N) {
        int4 idx4 = __ldcs(reinterpret_cast<const int4*>(index + j0));
        float4 v[8];
#pragma unroll
        for (int c = 0; c < 8; ++c)
            v[c] = __ldcs(reinterpret_cast<const float4*>(
                src + (size_t)(ch0 + c) * N + j0));

        int kk[4] = {idx4.x, idx4.y, idx4.z, idx4.w};
#pragma unroll
        for (int i = 0; i < 4; ++i) {
            unsigned long long lowkey = (unsigned)(N - (j0 + i));
            unsigned long long* ap = acc + (size_t)kk[i] * 16 + cc0;
#pragma unroll
            for (int c = 0; c < 8; ++c) {
                float fv = (i == 0) ? v[c].x : (i == 1) ? v[c].y
                                             : (i == 2) ? v[c].z : v[c].w;
                unsigned long long p =
                    ((unsigned long long)f2sort(fv) << 32) | lowkey;
                atomicMax(ap + c, p);
            }
        }
    } else {
        // tail: scalar per-point
        for (int i = 0; i < 4 && j0 + i < N; ++i) {
            int j = j0 + i;
            int k = __ldcs(index + j);
            unsigned long long lowkey = (unsigned)(N - j);
            unsigned long long* ap = acc + (size_t)k * 16 + cc0;
#pragma unroll
            for (int c = 0; c < 8; ++c) {
                float fv = __ldcs(src + (size_t)(ch0 + c) * N + j);
                unsigned long long p =
                    ((unsigned long long)f2sort(fv) << 32) | lowkey;
                atomicMax(ap + c, p);
            }
        }
    }
}

// -------------------- Pass 2: finalize (vectorized, 512 threads) --------------------
__global__ void finalize64_kernel(const float* __restrict__ src,
                                  float* __restrict__ out,
                                  float* __restrict__ arg,
                                  int N, int writeArg) {
    __shared__ __align__(16) float s_val[64][68];
    __shared__ __align__(16) float s_arg[64][68];
    int k0  = blockIdx.x * 64;
    int tid = threadIdx.x;
    size_t grpStride = (size_t)N * 16;

    if (k0 + 64 <= N) {
#pragma unroll
        for (int g = 0; g < 4; ++g) {
            const longlong2* accv = reinterpret_cast<const longlong2*>(
                g_acc + (size_t)g * grpStride + (size_t)k0 * 16);
            int idx = tid * 2;
            longlong2 p2 = __ldcs(accv + tid);
            int kk = idx >> 4;
            int c  = g * 16 + (idx & 15);
            {
                unsigned long long p = (unsigned long long)p2.x;
                unsigned low = (unsigned)p, hi = (unsigned)(p >> 32);
                s_val[c][kk] = low ? sort2f(hi) : __int_as_float(0xff800000);
                s_arg[c][kk] = (float)(low ? (N - (int)low) : N);
            }
            {
                unsigned long long p = (unsigned long long)p2.y;
                unsigned low = (unsigned)p, hi = (unsigned)(p >> 32);
                s_val[c + 1][kk] = low ? sort2f(hi) : __int_as_float(0xff800000);
                s_arg[c + 1][kk] = (float)(low ? (N - (int)low) : N);
            }
        }
        __syncthreads();

        float fN = (float)N;
#pragma unroll
        for (int i = 0; i < 2; ++i) {
            int e   = i * 2048 + tid * 4;
            int c   = e >> 6;
            int kk  = e & 63;
            size_t gidx = (size_t)c * N + (k0 + kk);
            float4 sv = __ldcs(reinterpret_cast<const float4*>(src + gidx));
            float4 sg = *reinterpret_cast<const float4*>(&s_val[c][kk]);
            float4 sa = *reinterpret_cast<const float4*>(&s_arg[c][kk]);
            float4 ov, av;
            ov.x = fmaxf(sv.x, sg.x); av.x = (sg.x >= sv.x) ? sa.x : fN;
            ov.y = fmaxf(sv.y, sg.y); av.y = (sg.y >= sv.y) ? sa.y : fN;
            ov.z = fmaxf(sv.z, sg.z); av.z = (sg.z >= sv.z) ? sa.z : fN;
            ov.w = fmaxf(sv.w, sg.w); av.w = (sg.w >= sv.w) ? sa.w : fN;
            __stcs(reinterpret_cast<float4*>(out + gidx), ov);
            if (writeArg) __stcs(reinterpret_cast<float4*>(arg + gidx), av);
        }
    } else {
        for (int e = tid; e < 64 * 64; e += blockDim.x) {
            int kk = e >> 6;
            int c  = e & 63;
            int k  = k0 + kk;
            float val = __int_as_float(0xff800000);
            int a = N;
            if (k < N) {
                int g  = c >> 4;
                int cc = c & 15;
                unsigned long long p =
                    g_acc[(size_t)g * grpStride + (size_t)k * 16 + cc];
                unsigned low = (unsigned)p, hi = (unsigned)(p >> 32);
                if (low) { val = sort2f(hi); a = N - (int)low; }
            }
            s_val[c][kk] = val;
            s_arg[c][kk] = (float)a;
        }
        __syncthreads();
        for (int e = tid; e < 64 * 64; e += blockDim.x) {
            int c  = e >> 6;
            int kk = e & 63;
            int k  = k0 + kk;
            if (k < N) {
                size_t idx = (size_t)c * N + k;
                float sv  = src[idx];
                float seg = s_val[c][kk];
                out[idx] = fmaxf(sv, seg);
                if (writeArg) arg[idx] = (seg >= sv) ? s_arg[c][kk] : (float)N;
            }
        }
    }
}

// -------------------- Generic fallback (C != 64) --------------------
__global__ void scatter_gen_kernel(const float* __restrict__ src,
                                   const int* __restrict__ index,
                                   int C, int N) {
    int j = blockIdx.x * blockDim.x + threadIdx.x;
    if (j >= N) return;
    int k = index[j];
    unsigned long long* accp = g_acc + (size_t)k * C;
    unsigned lowkey = (unsigned)(N - j);
    for (int c = 0; c < C; ++c) {
        float v = __ldg(src + (size_t)c * N + j);
        unsigned long long p =
            ((unsigned long long)f2sort(v) << 32) | (unsigned long long)lowkey;
        atomicMax(accp + c, p);
    }
}

__global__ void finalize_gen_kernel(const float* __restrict__ src,
                                    float* __restrict__ out,
                                    float* __restrict__ arg,
                                    int C, int N, int writeArg) {
    long long t = (long long)blockIdx.x * blockDim.x + threadIdx.x;
    long long total = (long long)C * N;
    if (t >= total) return;
    int c = (int)(t / N);
    int k = (int)(t % N);
    unsigned long long p = g_acc[(size_t)k * C + c];
    unsigned low = (unsigned)p, hi = (unsigned)(p >> 32);
    float seg = low ? sort2f(hi) : __int_as_float(0xff800000);
    int   a   = low ? (N - (int)low) : N;
    float sv = src[t];
    out[t] = fmaxf(sv, seg);
    if (writeArg) arg[t] = (float)((seg >= sv) ? a : N);
}

extern "C" void kernel_launch(void* const* d_in, const int* in_sizes, int n_in,
                              void* d_out, int out_size) {
    const float* src   = (const float*)d_in[0];
    const int*   index = (const int*)d_in[1];   // JAX x64-disabled: int32

    int N = in_sizes[1];
    int C = (N > 0) ? (in_sizes[0] / N) : 0;
    if (N <= 0 || C <= 0) return;

    size_t cn = (size_t)C * (size_t)N;

    unsigned char* accp = nullptr;
    cudaGetSymbolAddress((void**)&accp, g_acc);

    float* out = (float*)d_out;
    int writeArg = ((size_t)out_size >= 2 * cn) ? 1 : 0;
    float* arg = out + cn;

    if (C == 64) {
        size_t grpBytes = (size_t)N * 16 * sizeof(unsigned long long); // 64MB
        int sBlocks = (N + 511) / 512;   // 512 points per block (4 per thread)
        for (int g = 0; g < 4; ++g) {
            cudaMemsetAsync(accp + (size_t)g * grpBytes, 0, grpBytes, 0);
            scatter16_kernel<<<sBlocks, 256>>>(
                src, index, N, g * 16,
                reinterpret_cast<unsigned long long*>(accp + (size_t)g * grpBytes));
        }
        finalize64_kernel<<<(N + 63) / 64, 512>>>(src, out, arg, N, writeArg);
    } else {
        cudaMemsetAsync(accp, 0, cn * sizeof(unsigned long long), 0);
        int threads = 256;
        scatter_gen_kernel<<<(N + threads - 1) / threads, threads>>>(src, index, C, N);
        long long total = (long long)C * N;
        finalize_gen_kernel<<<(int)((total + threads - 1) / threads), threads>>>(
            src, out, arg, C, N, writeArg);
    }
}

// round 7
// speedup vs baseline: 1.8157x; 1.1043x over previous
#include <cuda_runtime.h>
#include <cstdint>

// Scratch: 4 channel-groups, each acc_g[k*16 + cc] packed
// (sortable_value:32 | (N-j):32). Group footprint = N*16*8B = 64MB (L2-resident).
__device__ unsigned long long g_acc[32000000];

__device__ __forceinline__ unsigned f2sort(float f) {
    unsigned u = __float_as_uint(f);
    return (u & 0x80000000u) ? ~u : (u | 0x80000000u);
}
__device__ __forceinline__ float sort2f(unsigned s) {
    unsigned u = (s & 0x80000000u) ? (s ^ 0x80000000u) : ~s;
    return __uint_as_float(u);
}

// -------------------- Pass 1: scatter, one channel-group (16 ch) --------------------
// Each thread: 4 consecutive points x 8 channels. src loads are LDG.128.
__global__ void scatter16_kernel(const float* __restrict__ src,
                                 const int* __restrict__ index,
                                 int N, int c0,
                                 unsigned long long* __restrict__ acc) {
    int t    = threadIdx.x;
    int half = t & 1;
    int g    = t >> 1;
    int j0   = blockIdx.x * 512 + g * 4;
    if (j0 >= N) return;
    int ch0 = c0 + half * 8;
    int cc0 = half * 8;

    if (j0 + 4 <= N) {
        int4 idx4 = __ldcs(reinterpret_cast<const int4*>(index + j0));
        float4 v[8];
#pragma unroll
        for (int c = 0; c < 8; ++c)
            v[c] = __ldcs(reinterpret_cast<const float4*>(
                src + (size_t)(ch0 + c) * N + j0));

        int kk[4] = {idx4.x, idx4.y, idx4.z, idx4.w};
#pragma unroll
        for (int i = 0; i < 4; ++i) {
            unsigned long long lowkey = (unsigned)(N - (j0 + i));
            unsigned long long* ap = acc + (size_t)kk[i] * 16 + cc0;
#pragma unroll
            for (int c = 0; c < 8; ++c) {
                float fv = (i == 0) ? v[c].x : (i == 1) ? v[c].y
                                             : (i == 2) ? v[c].z : v[c].w;
                unsigned long long p =
                    ((unsigned long long)f2sort(fv) << 32) | lowkey;
                atomicMax(ap + c, p);
            }
        }
    } else {
        for (int i = 0; i < 4 && j0 + i < N; ++i) {
            int j = j0 + i;
            int k = __ldcs(index + j);
            unsigned long long lowkey = (unsigned)(N - j);
            unsigned long long* ap = acc + (size_t)k * 16 + cc0;
#pragma unroll
            for (int c = 0; c < 8; ++c) {
                float fv = __ldcs(src + (size_t)(ch0 + c) * N + j);
                unsigned long long p =
                    ((unsigned long long)f2sort(fv) << 32) | lowkey;
                atomicMax(ap + c, p);
            }
        }
    }
}

// -------------------- Pass 2: per-group finalize (16 channels) --------------------
// Block handles a 64k x 16c tile of one group. acc_g is L2-hot (scatter just
// wrote it). Phase A: ll2 coalesced acc reads -> smem[cc][kk]. Phase B: float4
// src reads + float4 out/arg writes.
__global__ void finalize16_kernel(const float* __restrict__ src,
                                  float* __restrict__ out,
                                  float* __restrict__ arg,
                                  int N, int writeArg, int c0,
                                  const unsigned long long* __restrict__ acc) {
    __shared__ __align__(16) float s_val[16][68];
    __shared__ __align__(16) float s_arg[16][68];
    int k0  = blockIdx.x * 64;
    int tid = threadIdx.x;

    if (k0 + 64 <= N) {
        const longlong2* accv =
            reinterpret_cast<const longlong2*>(acc + (size_t)k0 * 16);
#pragma unroll
        for (int i = 0; i < 2; ++i) {
            int idx2 = i * 256 + tid;          // 0..511 ll2 in tile
            longlong2 p2 = __ldcs(accv + idx2);
            int e  = idx2 * 2;                  // element index kk*16+cc
            int kk = e >> 4;
            int cc = e & 15;
            {
                unsigned long long p = (unsigned long long)p2.x;
                unsigned low = (unsigned)p, hi = (unsigned)(p >> 32);
                s_val[cc][kk] = low ? sort2f(hi) : __int_as_float(0xff800000);
                s_arg[cc][kk] = (float)(low ? (N - (int)low) : N);
            }
            {
                unsigned long long p = (unsigned long long)p2.y;
                unsigned low = (unsigned)p, hi = (unsigned)(p >> 32);
                s_val[cc + 1][kk] = low ? sort2f(hi) : __int_as_float(0xff800000);
                s_arg[cc + 1][kk] = (float)(low ? (N - (int)low) : N);
            }
        }
        __syncthreads();

        float fN = (float)N;
        int c  = tid >> 4;            // 0..15
        int kk = (tid & 15) * 4;      // 0..60
        size_t gidx = (size_t)(c0 + c) * N + (k0 + kk);
        float4 sv = __ldcs(reinterpret_cast<const float4*>(src + gidx));
        float4 sg = *reinterpret_cast<const float4*>(&s_val[c][kk]);
        float4 sa = *reinterpret_cast<const float4*>(&s_arg[c][kk]);
        float4 ov, av;
        ov.x = fmaxf(sv.x, sg.x); av.x = (sg.x >= sv.x) ? sa.x : fN;
        ov.y = fmaxf(sv.y, sg.y); av.y = (sg.y >= sv.y) ? sa.y : fN;
        ov.z = fmaxf(sv.z, sg.z); av.z = (sg.z >= sv.z) ? sa.z : fN;
        ov.w = fmaxf(sv.w, sg.w); av.w = (sg.w >= sv.w) ? sa.w : fN;
        __stcs(reinterpret_cast<float4*>(out + gidx), ov);
        if (writeArg) __stcs(reinterpret_cast<float4*>(arg + gidx), av);
    } else {
        // partial tile: scalar guarded
        for (int e = tid; e < 64 * 16; e += blockDim.x) {
            int kk = e >> 4;
            int cc = e & 15;
            int k  = k0 + kk;
            float val = __int_as_float(0xff800000);
            int a = N;
            if (k < N) {
                unsigned long long p = acc[(size_t)k * 16 + cc];
                unsigned low = (unsigned)p, hi = (unsigned)(p >> 32);
                if (low) { val = sort2f(hi); a = N - (int)low; }
            }
            s_val[cc][kk] = val;
            s_arg[cc][kk] = (float)a;
        }
        __syncthreads();
        for (int e = tid; e < 16 * 64; e += blockDim.x) {
            int c  = e >> 6;
            int kk = e & 63;
            int k  = k0 + kk;
            if (k < N) {
                size_t idx = (size_t)(c0 + c) * N + k;
                float sv  = src[idx];
                float seg = s_val[c][kk];
                out[idx] = fmaxf(sv, seg);
                if (writeArg) arg[idx] = (seg >= sv) ? s_arg[c][kk] : (float)N;
            }
        }
    }
}

// -------------------- Generic fallback (C != 64) --------------------
__global__ void scatter_gen_kernel(const float* __restrict__ src,
                                   const int* __restrict__ index,
                                   int C, int N) {
    int j = blockIdx.x * blockDim.x + threadIdx.x;
    if (j >= N) return;
    int k = index[j];
    unsigned long long* accp = g_acc + (size_t)k * C;
    unsigned lowkey = (unsigned)(N - j);
    for (int c = 0; c < C; ++c) {
        float v = __ldg(src + (size_t)c * N + j);
        unsigned long long p =
            ((unsigned long long)f2sort(v) << 32) | (unsigned long long)lowkey;
        atomicMax(accp + c, p);
    }
}

__global__ void finalize_gen_kernel(const float* __restrict__ src,
                                    float* __restrict__ out,
                                    float* __restrict__ arg,
                                    int C, int N, int writeArg) {
    long long t = (long long)blockIdx.x * blockDim.x + threadIdx.x;
    long long total = (long long)C * N;
    if (t >= total) return;
    int c = (int)(t / N);
    int k = (int)(t % N);
    unsigned long long p = g_acc[(size_t)k * C + c];
    unsigned low = (unsigned)p, hi = (unsigned)(p >> 32);
    float seg = low ? sort2f(hi) : __int_as_float(0xff800000);
    int   a   = low ? (N - (int)low) : N;
    float sv = src[t];
    out[t] = fmaxf(sv, seg);
    if (writeArg) arg[t] = (float)((seg >= sv) ? a : N);
}

extern "C" void kernel_launch(void* const* d_in, const int* in_sizes, int n_in,
                              void* d_out, int out_size) {
    const float* src   = (const float*)d_in[0];
    const int*   index = (const int*)d_in[1];   // JAX x64-disabled: int32

    int N = in_sizes[1];
    int C = (N > 0) ? (in_sizes[0] / N) : 0;
    if (N <= 0 || C <= 0) return;

    size_t cn = (size_t)C * (size_t)N;

    unsigned char* accp = nullptr;
    cudaGetSymbolAddress((void**)&accp, g_acc);

    float* out = (float*)d_out;
    int writeArg = ((size_t)out_size >= 2 * cn) ? 1 : 0;
    float* arg = out + cn;

    if (C == 64) {
        // lazy one-time stream/event creation (host objects only)
        static bool s_init = false;
        static cudaStream_t s1;
        static cudaEvent_t evS[4], evJ;
        if (!s_init) {
            cudaStreamCreateWithFlags(&s1, cudaStreamNonBlocking);
            for (int i = 0; i < 4; ++i)
                cudaEventCreateWithFlags(&evS[i], cudaEventDisableTiming);
            cudaEventCreateWithFlags(&evJ, cudaEventDisableTiming);
            s_init = true;
        }

        size_t grpBytes = (size_t)N * 16 * sizeof(unsigned long long); // 64MB
        int sBlocks = (N + 511) / 512;
        int fBlocks = (N + 63) / 64;

        for (int g = 0; g < 4; ++g) {
            unsigned long long* acc_g =
                reinterpret_cast<unsigned long long*>(accp + (size_t)g * grpBytes);
            cudaMemsetAsync(accp + (size_t)g * grpBytes, 0, grpBytes, 0);
            scatter16_kernel<<<sBlocks, 256, 0, 0>>>(src, index, N, g * 16, acc_g);
            cudaEventRecord(evS[g], 0);
            cudaStreamWaitEvent(s1, evS[g], 0);
            finalize16_kernel<<<fBlocks, 256, 0, s1>>>(
                src, out, arg, N, writeArg, g * 16, acc_g);
        }
        cudaEventRecord(evJ, s1);
        cudaStreamWaitEvent(0, evJ, 0);
    } else {
        cudaMemsetAsync(accp, 0, cn * sizeof(unsigned long long), 0);
        int threads = 256;
        scatter_gen_kernel<<<(N + threads - 1) / threads, threads>>>(src, index, C, N);
        long long total = (long long)C * N;
        finalize_gen_kernel<<<(int)((total + threads - 1) / threads), threads>>>(
            src, out, arg, C, N, writeArg);
    }
}